// round 16
// baseline (speedup 1.0000x reference)
#include <cuda_runtime.h>
#include <cuda_bf16.h>
#include <math.h>

// ---------------- static configuration ----------------
#define Bn     32
#define Tn     4096
#define Cn     3
#define NSC    128
#define NPSI   4096
#define PADL   2047
#define LP     8190           // Tn + 2*PADL
#define DXSTR  8192
#define NROW   96             // Cn * Bn
#define OUTH   224
#define OUTW   224
#define OUTN   (Bn*OUTH*OUTW*Cn)

#define U0     384            // global u-grid origin
#define KE     3456           // Ê u-extent (64-aligned)
#define MTOT   896            // 128 scales x 7 interior classes
#define KMAX   3268           // >= max wavelet kernel length 3265
#define KSTR   3280           // g_kern row stride
#define EKE    3328           // edge-kernel stride (fixup)

#define BM     128
#define BN     128
#define NT     24             // 3072 / BN
#define KC     512            // split-K chunk (16 slabs of 32)
#define MAXCH  26             // chunk table capacity (real ~19)
#define NTOTAL 3072           // 96 rows x 32 j
#define DXTOT  (NROW * DXSTR)

#define BUFSZ  40960          // Ah(10240)+Al(10240)+Bh(10240)+Bl(10240)
#define AHo    0
#define ALo    10240
#define BHo    20480
#define BLo    30720

// ---------------- device scratch ----------------
__device__ __align__(16) float g_dx[DXTOT + 4096];                   // 3 MB f32 (fixup)
__device__ __align__(16) __nv_bfloat16 g_dxh[DXTOT + 4096];          // 1.5 MB
__device__ __align__(16) __nv_bfloat16 g_dxl[DXTOT + 4096];          // 1.5 MB
__device__ __align__(16) float g_kern[NSC * KSTR];                   // gathered kernels
__device__ __align__(16) __nv_bfloat16 g_ehh[(size_t)MTOT * KE + 64];// 6.2 MB [m][k] hi
__device__ __align__(16) __nv_bfloat16 g_ehl[(size_t)MTOT * KE + 64];// 6.2 MB [m][k] lo
__device__ __align__(16) float g_eke[NSC * 2 * EKE];                 // edge kernels f32
__device__ __align__(16) float g_part[(size_t)MAXCH * BM * NTOTAL];  // 41 MB partials
__device__ float  g_tmpA[NSC * NROW * OUTW];                         // 11 MB
__device__ int    g_n[NSC];
__device__ int    g_d0[NSC];
__device__ float  g_nsq[NSC];
__device__ float  g_wt[OUTW * 40];
__device__ int    g_wst[OUTW];
__device__ int    g_wcnt[OUTW];
__device__ int    g_whi[OUTH * 2];
__device__ float  g_whw[OUTH * 2];
__device__ int    g_tk[7 * 2];
__device__ int    g_chk[MAXCH * 2];
__device__ int    g_chklen[MAXCH];
__device__ int    g_nchk;
__device__ int    g_tfirst[7];
__device__ int    g_tcnt[7];

// ---------------- helpers ----------------
__device__ __forceinline__ unsigned smem_u32(const void* p) {
    unsigned a;
    asm("{ .reg .u64 t; cvta.to.shared.u64 t, %1; cvt.u32.u64 %0, t; }" : "=r"(a) : "l"(p));
    return a;
}
#define CP16(dst, src) \
    asm volatile("cp.async.cg.shared.global [%0], [%1], 16;" :: "r"(dst), "l"(src) : "memory")
#define CP_COMMIT() asm volatile("cp.async.commit_group;" ::: "memory")
#define CP_WAIT0()  asm volatile("cp.async.wait_group 0;" ::: "memory")

// ---------------- per-scale parameters (exact double formula) ----------------
__device__ __forceinline__ void scale_param(int s, int* n_out, int* d0_out,
                                            double* den_out, float* sf_out) {
    double l2 = log10(2.0), lM = log10(204.0);
    double y = (s == NSC - 1) ? lM : (l2 + (double)s * ((lM - l2) / (double)(NSC - 1)));
    float  sf = (float)pow(10.0, y);
    double sd = (double)sf;
    int n = (int)ceil(sd * 16.0 + 1.0);
    int d0 = (4094 - n) / 2; if (d0 < 0) d0 = 0;
    *n_out = n; *d0_out = d0;
    if (den_out) *den_out = sd * (16.0 / 4095.0);
    if (sf_out)  *sf_out = sf;
}

__device__ __forceinline__ float xp_val(const float* __restrict__ x, int b, int c, int p) {
    int i = p - PADL;
    if (i < 0) i = -i;
    else if (i >= Tn) i = 2 * (Tn - 1) - i;
    return x[((size_t)b * Tn + i) * Cn + c];
}

// ---------------- prep: scales+tables (block 0), gather, dx (all fused) ----------------
__global__ __launch_bounds__(256) void k_prep(const float* __restrict__ psi,
                                              const float* __restrict__ x) {
    int sc = blockIdx.x;
    int tid = threadIdx.x;

    int n, d0; double den; float sf;
    scale_param(sc, &n, &d0, &den, &sf);
    if (tid == 0) {
        g_n[sc] = n; g_d0[sc] = d0; g_nsq[sc] = -sqrtf(sf);
    }
    for (int k = tid; k < n; k += 256) {
        int m = n - 1 - k;                                  // flip
        int j = (int)floor((double)m / den);
        if (j < 0) j = 0;
        if (j > NPSI - 1) j = NPSI - 1;
        g_kern[sc * KSTR + k] = psi[j];
    }
    // dx slice (grid-stride across the 128 blocks)
    for (int idx = sc * 256 + tid; idx < DXTOT; idx += NSC * 256) {
        int r = idx >> 13;
        int p = idx & (DXSTR - 1);
        int c = r / Bn, b = r % Bn;
        float v = 0.0f;
        if (p <= LP - 2) v = xp_val(x, b, c, p + 1) - xp_val(x, b, c, p);
        g_dx[idx] = v;
        __nv_bfloat16 h = __float2bfloat16(v);
        g_dxh[idx] = h;
        g_dxl[idx] = __float2bfloat16(v - __bfloat162float(h));
    }
    if (blockIdx.x != 0) return;

    // ---- block 0: resize weights + tile tables ----
    if (tid < OUTW) {
        double inv = 4096.0 / 224.0;
        double ks  = inv;
        double sfd = ((double)tid + 0.5) * inv - 0.5;
        int lo = (int)ceil(sfd - ks);  if (lo < 0) lo = 0;
        int hi = (int)floor(sfd + ks); if (hi > Tn - 1) hi = Tn - 1;
        double tot = 0.0;
        for (int i = lo; i <= hi; i++) {
            double w = 1.0 - fabs((double)i - sfd) / ks; if (w < 0.0) w = 0.0;
            tot += w;
        }
        int cnt = hi - lo + 1;
        g_wst[tid] = lo; g_wcnt[tid] = cnt;
        for (int j = 0; j < cnt; j++) {
            double w = 1.0 - fabs((double)(lo + j) - sfd) / ks; if (w < 0.0) w = 0.0;
            g_wt[tid * 40 + j] = (float)(w / tot);
        }
        for (int j = cnt; j < 40; j++) g_wt[tid * 40 + j] = 0.0f;
    }
    if (tid < OUTH) {
        double inv = 128.0 / 224.0;
        double sfd = ((double)tid + 0.5) * inv - 0.5;
        int ia = (int)floor(sfd);
        int i0 = ia, i1 = ia + 1;
        double w0 = 1.0 - (sfd - (double)ia);
        double w1 = sfd - (double)ia;
        bool v0 = (i0 >= 0 && i0 < NSC);
        bool v1 = (i1 >= 0 && i1 < NSC);
        double tot = (v0 ? w0 : 0.0) + (v1 ? w1 : 0.0);
        int   o0 = v0 ? i0 : (v1 ? i1 : 0);
        int   o1 = v1 ? i1 : (v0 ? i0 : 0);
        float f0 = v0 ? (float)(w0 / tot) : 0.0f;
        float f1 = v1 ? (float)(w1 / tot) : 0.0f;
        if (!v0 && v1) { f0 = (float)(w1 / tot); f1 = 0.0f; }
        g_whi[tid * 2 + 0] = o0; g_whi[tid * 2 + 1] = o1;
        g_whw[tid * 2 + 0] = f0; g_whw[tid * 2 + 1] = f1;
    }
    __syncthreads();
    if (tid < 7) {
        int smin = (BM * tid) / 7;
        int smax = (BM * tid + BM - 1) / 7; if (smax > NSC - 1) smax = NSC - 1;
        int lo = 1 << 30, hi = 0;
        for (int s = smin; s <= smax; s++) {
            int ns, ds; scale_param(s, &ns, &ds, 0, 0);
            for (int c = 0; c < 7; c++) {
                int A = ds + g_wst[7 + c] - 128;
                int e = A + ns + g_wcnt[7 + c] - 1;
                int a0 = A - U0, e0 = e + 1 - U0;
                if (a0 < lo) lo = a0;
                if (e0 > hi) hi = e0;
            }
        }
        if (lo < 0) lo = 0;
        int hi64 = (hi + 63) & ~63; if (hi64 > KE) hi64 = KE;
        g_tk[tid * 2 + 0] = lo & ~63;
        g_tk[tid * 2 + 1] = hi64;
    }
    __syncthreads();
    if (tid == 0) {
        int nc = 0;
        for (int q = 0; q < 7; q++) {
            int mt = 6 - q;                       // heavy tiles first
            int klo = g_tk[mt * 2], khi = g_tk[mt * 2 + 1];
            g_tfirst[mt] = nc;
            int cnt = 0;
            for (int k = klo; k < khi && nc < MAXCH; k += KC) {
                int len = khi - k; if (len > KC) len = KC;
                g_chk[nc * 2 + 0] = mt;
                g_chk[nc * 2 + 1] = k;
                g_chklen[nc] = len;
                nc++; cnt++;
            }
            g_tcnt[mt] = cnt;
        }
        g_nchk = nc;
    }
}

// ---------------- build resize-folded kernels (bf16 hi/lo for interior) ----------------
__global__ __launch_bounds__(256) void k_ebuildc() {
    __shared__ float skern[KMAX];
    __shared__ float swt[40];
    int cls = blockIdx.x;
    int sc  = blockIdx.y;
    int tid = threadIdx.x;
    int n = g_n[sc], d0 = g_d0[sc];
    float nsq = g_nsq[sc];
    int wrep = (cls < 7) ? (7 + cls) : ((cls == 7) ? 0 : 223);
    int st = g_wst[wrep], cnt = g_wcnt[wrep];

    for (int k = tid; k < n; k += 256) skern[k] = g_kern[sc * KSTR + k];
    if (tid < 40) swt[tid] = g_wt[wrep * 40 + tid];
    __syncthreads();

    int len = n + cnt - 1;
    if (cls < 7) {
        int A = d0 + st - 128;
        int m = sc * 7 + cls;
        int p0 = A - U0;
        for (int v = tid; v < KE; v += 256) {
            int p = v - p0;
            float acc = 0.0f;
            if (p >= 0 && p < len) {
                int t0 = p - (n - 1); if (t0 < 0) t0 = 0;
                int t1 = p; if (t1 > cnt - 1) t1 = cnt - 1;
                for (int t = t0; t <= t1; t++) acc += swt[t] * skern[p - t];
                acc *= nsq;
            }
            __nv_bfloat16 h = __float2bfloat16(acc);
            g_ehh[(size_t)m * KE + v] = h;
            g_ehl[(size_t)m * KE + v] = __float2bfloat16(acc - __bfloat162float(h));
        }
    } else {
        int sh = (d0 + st) & 3;
        float* dst = g_eke + (size_t)(sc * 2 + (cls - 7)) * EKE;
        for (int v = tid; v < EKE; v += 256) {
            int p = v - sh;
            float acc = 0.0f;
            if (p >= 0 && p < len) {
                int t0 = p - (n - 1); if (t0 < 0) t0 = 0;
                int t1 = p; if (t1 > cnt - 1) t1 = cnt - 1;
                for (int t = t0; t <= t1; t++) acc += swt[t] * skern[p - t];
                acc *= nsq;
            }
            dst[v] = acc;
        }
    }
}

// ---------------- HMMA GEMM: BM=128 x BN=128, 256 thr, cp.async double-buffered ----------------
#define MMA16816(d, a0, a1, a2, a3, b0, b1)                                         \
    asm volatile(                                                                   \
        "mma.sync.aligned.m16n8k16.row.col.f32.bf16.bf16.f32 "                      \
        "{%0,%1,%2,%3}, {%4,%5,%6,%7}, {%8,%9}, {%0,%1,%2,%3};"                     \
        : "+f"(d[0]), "+f"(d[1]), "+f"(d[2]), "+f"(d[3])                            \
        : "r"(a0), "r"(a1), "r"(a2), "r"(a3), "r"(b0), "r"(b1))

__global__ __launch_bounds__(256) void k_gemm_mma() {
    extern __shared__ char smc[];

    int chunk = blockIdx.y;
    if (chunk >= g_nchk) return;
    int mt  = g_chk[chunk * 2 + 0];
    int klo = g_chk[chunk * 2 + 1];
    int nslab = g_chklen[chunk] >> 5;
    int nt = blockIdx.x;
    int m0 = mt * BM, n0 = nt * BN;
    int tid = threadIdx.x;
    int wid = tid >> 5, lane = tid & 31;
    int g = lane >> 2, tig = lane & 3;
    int R  = (wid & 3) * 32;                        // warp m-base
    int Cb = (wid >> 2) * 64;                       // warp n-base

    unsigned sbase = smem_u32(smc);
    int srow = tid >> 2, sq = tid & 3;              // staging coords

    auto stage = [&](int s, int buf) {
        int koff = klo + s * 32;
        unsigned sb = sbase + buf * BUFSZ;
        #pragma unroll
        for (int pass = 0; pass < 2; pass++) {
            int row = srow + pass * 64;
            size_t gsrc = ((size_t)(m0 + row) * KE + koff + sq * 8) * 2;
            unsigned dst = sb + AHo + row * 80 + sq * 16;
            CP16(dst, (const char*)g_ehh + gsrc);
            CP16(dst + (ALo - AHo), (const char*)g_ehl + gsrc);
        }
        #pragma unroll
        for (int pass = 0; pass < 2; pass++) {
            int row = srow + pass * 64;
            int n = n0 + row;
            int drow = n >> 5, j = n & 31;
            size_t gsrc = ((size_t)drow * DXSTR + U0 + koff + 128 * j + sq * 8) * 2;
            unsigned dst = sb + BHo + row * 80 + sq * 16;
            CP16(dst, (const char*)g_dxh + gsrc);
            CP16(dst + (BLo - BHo), (const char*)g_dxl + gsrc);
        }
        CP_COMMIT();
    };

    float acc[2][8][4];
    #pragma unroll
    for (int mi = 0; mi < 2; mi++)
        #pragma unroll
        for (int ni = 0; ni < 8; ni++) {
            acc[mi][ni][0] = 0.f; acc[mi][ni][1] = 0.f;
            acc[mi][ni][2] = 0.f; acc[mi][ni][3] = 0.f;
        }

    stage(0, 0);
    CP_WAIT0();
    __syncthreads();

    for (int s = 0; s < nslab; s++) {
        int cur = s & 1;
        if (s + 1 < nslab) stage(s + 1, cur ^ 1);

        const unsigned* wAh = (const unsigned*)(smc + cur * BUFSZ + AHo);
        const unsigned* wAl = (const unsigned*)(smc + cur * BUFSZ + ALo);
        const unsigned* wBh = (const unsigned*)(smc + cur * BUFSZ + BHo);
        const unsigned* wBl = (const unsigned*)(smc + cur * BUFSZ + BLo);

        #pragma unroll
        for (int ks = 0; ks < 2; ks++) {
            int kw = ks * 8;
            unsigned aH[2][4], aL[2][4];
            #pragma unroll
            for (int mi = 0; mi < 2; mi++) {
                int r0 = (R + mi * 16 + g) * 20 + tig + kw;
                int r8 = r0 + 8 * 20;
                aH[mi][0] = wAh[r0];     aH[mi][1] = wAh[r8];
                aH[mi][2] = wAh[r0 + 4]; aH[mi][3] = wAh[r8 + 4];
                aL[mi][0] = wAl[r0];     aL[mi][1] = wAl[r8];
                aL[mi][2] = wAl[r0 + 4]; aL[mi][3] = wAl[r8 + 4];
            }
            #pragma unroll
            for (int ni = 0; ni < 8; ni++) {
                int b0i = (Cb + ni * 8 + g) * 20 + tig + kw;
                unsigned bh0 = wBh[b0i], bh1 = wBh[b0i + 4];
                unsigned bl0 = wBl[b0i], bl1 = wBl[b0i + 4];
                #pragma unroll
                for (int mi = 0; mi < 2; mi++) {
                    MMA16816(acc[mi][ni], aH[mi][0], aH[mi][1], aH[mi][2], aH[mi][3], bh0, bh1);
                    MMA16816(acc[mi][ni], aH[mi][0], aH[mi][1], aH[mi][2], aH[mi][3], bl0, bl1);
                    MMA16816(acc[mi][ni], aL[mi][0], aL[mi][1], aL[mi][2], aL[mi][3], bh0, bh1);
                }
            }
        }

        if (s + 1 < nslab) CP_WAIT0();
        __syncthreads();
    }

    float* pp = g_part + ((size_t)chunk * BM) * NTOTAL + n0;
    #pragma unroll
    for (int mi = 0; mi < 2; mi++) {
        int mrow = R + mi * 16 + g;
        #pragma unroll
        for (int ni = 0; ni < 8; ni++) {
            int nc = Cb + ni * 8 + tig * 2;
            *(float2*)(pp + (size_t)mrow * NTOTAL + nc) =
                make_float2(acc[mi][ni][0], acc[mi][ni][1]);
            *(float2*)(pp + (size_t)(mrow + 8) * NTOTAL + nc) =
                make_float2(acc[mi][ni][2], acc[mi][ni][3]);
        }
    }
}

// ---------------- fused split-K reduction + permute into g_tmpA ----------------
__global__ __launch_bounds__(224) void k_redtr2() {
    __shared__ float sm[224];
    int sc  = blockIdx.x;
    int row = blockIdx.y;
    int t = threadIdx.x;
    int cc = t >> 5, jj = t & 31;
    int m = sc * 7 + cc;
    int mt = m >> 7, ml = m & 127;
    int first = g_tfirst[mt], cnt = g_tcnt[mt];
    float s = 0.f;
    for (int c = 0; c < cnt; c++)
        s += g_part[((size_t)(first + c) * BM + ml) * NTOTAL + row * 32 + jj];
    sm[cc * 32 + jj] = s;
    __syncthreads();
    int w = t;
    int j2 = w / 7, c2 = w - j2 * 7;
    g_tmpA[(sc * NROW + row) * OUTW + w] = sm[c2 * 32 + j2];
}

// ---------------- exact fixup for clipped edge columns w=0, w=223 ----------------
__global__ void k_fixup() {
    __shared__ float se[EKE];
    int e  = blockIdx.x;
    int sc = blockIdx.y;
    int tid = threadIdx.x;
    int wE = e ? 223 : 0;
    int n = g_n[sc], d0 = g_d0[sc];
    int st = g_wst[wE], cnt = g_wcnt[wE];
    int base = (d0 + st) & ~3;
    int sh = (d0 + st) & 3;
    int qmax = sh + n + cnt - 1;

    const float* esrc = g_eke + (size_t)(sc * 2 + e) * EKE;
    for (int i = tid * 4; i < EKE; i += 1024)
        *(float4*)(se + i) = *(const float4*)(esrc + i);
    __syncthreads();

    int wi = tid >> 5, lane = tid & 31;
    for (int row = wi; row < NROW; row += 8) {
        const float* dxr = g_dx + (size_t)row * DXSTR + base;
        float p = 0.f;
        for (int q = lane * 4; q < qmax; q += 128) {
            float4 d = *(const float4*)(dxr + q);
            float4 ev = *(const float4*)(se + q);
            p = fmaf(d.x, ev.x, fmaf(d.y, ev.y, fmaf(d.z, ev.z, fmaf(d.w, ev.w, p))));
        }
        #pragma unroll
        for (int o = 16; o > 0; o >>= 1) p += __shfl_xor_sync(0xffffffffu, p, o);
        if (lane == 0) g_tmpA[(sc * NROW + row) * OUTW + wE] = p;
    }
}

// ---------------- resize stage B: scale axis 128 -> 224 ----------------
__global__ void k_resize_h(float* __restrict__ out) {
    int idx = blockIdx.x * blockDim.x + threadIdx.x;
    if (idx >= OUTN) return;
    int c = idx % Cn;
    int w = (idx / Cn) % OUTW;
    int h = (idx / (Cn * OUTW)) % OUTH;
    int b = idx / (Cn * OUTW * OUTH);
    int i0 = g_whi[h * 2 + 0], i1 = g_whi[h * 2 + 1];
    float f0 = g_whw[h * 2 + 0], f1 = g_whw[h * 2 + 1];
    int rb = (c * Bn + b) * OUTW + w;
    out[idx] = f0 * g_tmpA[i0 * NROW * OUTW + rb] + f1 * g_tmpA[i1 * NROW * OUTW + rb];
}

// ---------------- launch ----------------
extern "C" void kernel_launch(void* const* d_in, const int* in_sizes, int n_in,
                              void* d_out, int out_size) {
    const float* x   = (const float*)d_in[0];       // (32, 4096, 3) f32
    const float* psi = (const float*)d_in[1];       // (4096,) f32
    float* out = (float*)d_out;

    static int smem_set = 0;
    if (!smem_set) {
        cudaFuncSetAttribute(k_gemm_mma, cudaFuncAttributeMaxDynamicSharedMemorySize,
                             2 * BUFSZ);
        smem_set = 1;
    }

    k_prep<<<NSC, 256>>>(psi, x);                        // 0: scales+gather+dx+tables
    k_ebuildc<<<dim3(9, NSC), 256>>>();                  // 1
    k_gemm_mma<<<dim3(NT, MAXCH), 256, 2 * BUFSZ>>>();   // 2
    k_redtr2<<<dim3(NSC, NROW), 224>>>();                // 3: ncu slot -> measure blob
    k_fixup<<<dim3(2, NSC), 256>>>();                    // 4
    k_resize_h<<<(OUTN + 255) / 256, 256>>>(out);        // 5
}